// round 9
// baseline (speedup 1.0000x reference)
#include <cuda_runtime.h>
#include <cuda_fp16.h>
#include <math.h>

#define NN 100000
#define NE 6400000
#define F1 5     // F_IN
#define F2 5     // F_HID
#define F3 10    // F_OUT

// Scratch (no allocations allowed)
// Packed fp16 gather table: 8 halfs/node = 16B: [f0 f1 f2 f3 f4 degslot pad pad]
__device__ uint4 g_gath16[NN];
// Separate accumulators per layer (node1 never has to re-zero; deg lives in acc1)
__device__ uint4 g_acc1[NN];
__device__ uint4 g_acc2[NN];
// Full-precision h for the layer-2 self term
__device__ float g_h32[NN * F2];

__device__ __forceinline__ float sigmoidf_(float z) {
    return 1.0f / (1.0f + __expf(-z));
}

__device__ __forceinline__ unsigned packh2(float a, float b) {
    unsigned lo = __half_as_ushort(__float2half_rn(a));
    unsigned hi = __half_as_ushort(__float2half_rn(b));
    return lo | (hi << 16);
}
__device__ __forceinline__ float loh(unsigned w) {
    return __half2float(__ushort_as_half((unsigned short)(w & 0xFFFF)));
}
__device__ __forceinline__ float hih(unsigned w) {
    return __half2float(__ushort_as_half((unsigned short)(w >> 16)));
}

// Single 16B half-precision vector reduction: 8 half lanes in one LTS op.
__device__ __forceinline__ void red_v4h2(uint4* p, unsigned a, unsigned b,
                                         unsigned c, unsigned d) {
    asm volatile("red.global.add.noftz.v4.f16x2 [%0], {%1, %2, %3, %4};"
                 :: "l"(p), "r"(a), "r"(b), "r"(c), "r"(d) : "memory");
}

// Prep: zero both accumulators, quantize x into packed gather table
__global__ void k_prep(const float* __restrict__ x) {
    cudaTriggerProgrammaticLaunchCompletion();
    int v = blockIdx.x * blockDim.x + threadIdx.x;
    if (v >= NN) return;
    const float* xs = x + v * F1;
    unsigned w0 = packh2(xs[0], xs[1]);
    unsigned w1 = packh2(xs[2], xs[3]);
    unsigned w2 = packh2(xs[4], 0.0f);   // deg slot starts at 0
    g_gath16[v] = make_uint4(w0, w1, w2, 0u);
    g_acc1[v]   = make_uint4(0u, 0u, 0u, 0u);
    g_acc2[v]   = make_uint4(0u, 0u, 0u, 0u);
}

// Edge pass: acc[dst] += gath16[src], one LDG.128 + one red.v4.f16x2 per edge.
// Index loads happen BEFORE the grid-dependency sync (independent of the
// predecessor kernel) so they overlap its execution under PDL.
// DEG=1: also add 1.0h into the deg lane (high half of word 2).
template <int DEG>
__global__ void __launch_bounds__(256) k_edge(const int4* __restrict__ src4,
                                              const int4* __restrict__ dst4,
                                              uint4* __restrict__ acc) {
    cudaTriggerProgrammaticLaunchCompletion();
    int t = blockIdx.x * blockDim.x + threadIdx.x;
    int4 s4 = make_int4(0, 0, 0, 0), d4 = make_int4(0, 0, 0, 0);
    bool act = t < NE / 4;
    if (act) { s4 = __ldg(src4 + t); d4 = __ldg(dst4 + t); }
    cudaGridDependencySynchronize();   // wait for predecessor's table/zeroing
    if (!act) return;
    int ss[4] = {s4.x, s4.y, s4.z, s4.w};
    int dd[4] = {d4.x, d4.y, d4.z, d4.w};
    const unsigned degbit = DEG ? 0x3C000000u : 0u;   // +1.0h in deg lane
    uint4 g[4];
#pragma unroll
    for (int k = 0; k < 4; k++) g[k] = __ldg(&g_gath16[ss[k]]);
#pragma unroll
    for (int k = 0; k < 4; k++) {
        red_v4h2(&acc[dd[k]], g[k].x, g[k].y, g[k].z | degbit, g[k].w);
    }
}

// Node pass 1: h = sigmoid(x @ Ws1 + (acc1/deg) @ Wn1 + b1)
// Writes: fp32 h (self term of layer 2), packed CENTERED h-0.5 (gather table).
// acc1 left intact (deg lane consumed again by node2).
__global__ void k_node1(const float* __restrict__ x,
                        const float* __restrict__ Ws,
                        const float* __restrict__ Wn,
                        const float* __restrict__ b) {
    cudaTriggerProgrammaticLaunchCompletion();
    int v = blockIdx.x * blockDim.x + threadIdx.x;
    float xs[F1], wS[F1 * F2], wN[F1 * F2], bb[F2];
    if (v < NN) {
#pragma unroll
        for (int i = 0; i < F1; i++) xs[i] = x[v * F1 + i];
#pragma unroll
        for (int i = 0; i < F1 * F2; i++) { wS[i] = __ldg(Ws + i); wN[i] = __ldg(Wn + i); }
#pragma unroll
        for (int j = 0; j < F2; j++) bb[j] = __ldg(b + j);
    }
    cudaGridDependencySynchronize();   // wait for edge1's reds
    if (v >= NN) return;
    uint4 a = g_acc1[v];
    float deg = hih(a.z);
    float inv = 1.0f / fmaxf(deg, 1.0f);
    float xn[F1] = { loh(a.x) * inv, hih(a.x) * inv,
                     loh(a.y) * inv, hih(a.y) * inv,
                     loh(a.z) * inv };
    float h[F2];
#pragma unroll
    for (int j = 0; j < F2; j++) {
        float z = bb[j];
#pragma unroll
        for (int i = 0; i < F1; i++) {
            z = fmaf(xs[i], wS[i * F2 + j], z);
            z = fmaf(xn[i], wN[i * F2 + j], z);
        }
        h[j] = sigmoidf_(z);
    }
#pragma unroll
    for (int j = 0; j < F2; j++) g_h32[v * F2 + j] = h[j];
    // Centered h-0.5 keeps fp16 sums small (|sum| ~ sqrt(deg)/4, not deg/2)
    unsigned w0 = packh2(h[0] - 0.5f, h[1] - 0.5f);
    unsigned w1 = packh2(h[2] - 0.5f, h[3] - 0.5f);
    unsigned w2 = packh2(h[4] - 0.5f, 0.0f);
    g_gath16[v] = make_uint4(w0, w1, w2, 0u);
}

// Node pass 2: out = sigmoid(h @ Ws2 + (acc2_c/deg + 0.5) @ Wn2 + b2)
// deg comes from acc1 (untouched since pass 1).
__global__ void k_node2(float* __restrict__ out,
                        const float* __restrict__ Ws,
                        const float* __restrict__ Wn,
                        const float* __restrict__ b) {
    cudaTriggerProgrammaticLaunchCompletion();
    int v = blockIdx.x * blockDim.x + threadIdx.x;
    float wS[F2 * F3], wN[F2 * F3], bb[F3];
    if (v < NN) {
#pragma unroll
        for (int i = 0; i < F2 * F3; i++) { wS[i] = __ldg(Ws + i); wN[i] = __ldg(Wn + i); }
#pragma unroll
        for (int j = 0; j < F3; j++) bb[j] = __ldg(b + j);
    }
    cudaGridDependencySynchronize();   // wait for edge2's reds
    if (v >= NN) return;
    uint4 a = g_acc2[v];
    float deg = hih(__ldg((const unsigned*)&g_acc1[v].z - 0) ? g_acc1[v].z : g_acc1[v].z);
    deg = hih(g_acc1[v].z);
    float inv = 1.0f / fmaxf(deg, 1.0f);
    // De-center: mean(h) = mean(h-0.5) + 0.5  (only where deg>0; deg==0 must give 0)
    float half_off = (deg > 0.0f) ? 0.5f : 0.0f;
    float hn[F2] = { loh(a.x) * inv + half_off, hih(a.x) * inv + half_off,
                     loh(a.y) * inv + half_off, hih(a.y) * inv + half_off,
                     loh(a.z) * inv + half_off };
    float hs[F2];
#pragma unroll
    for (int i = 0; i < F2; i++) hs[i] = g_h32[v * F2 + i];
#pragma unroll
    for (int j = 0; j < F3; j++) {
        float z = bb[j];
#pragma unroll
        for (int i = 0; i < F2; i++) {
            z = fmaf(hs[i], wS[i * F3 + j], z);
            z = fmaf(hn[i], wN[i * F3 + j], z);
        }
        out[v * F3 + j] = sigmoidf_(z);
    }
}

static inline void launch_pdl(void* fn, dim3 grid, dim3 block,
                              void** args, bool pdl) {
    cudaLaunchConfig_t cfg = {};
    cfg.gridDim = grid;
    cfg.blockDim = block;
    cfg.dynamicSmemBytes = 0;
    cfg.stream = 0;
    cudaLaunchAttribute attr[1];
    if (pdl) {
        attr[0].id = cudaLaunchAttributeProgrammaticStreamSerialization;
        attr[0].val.programmaticStreamSerializationAllowed = 1;
        cfg.attrs = attr;
        cfg.numAttrs = 1;
    }
    cudaLaunchKernelExC(&cfg, fn, args);
}

extern "C" void kernel_launch(void* const* d_in, const int* in_sizes, int n_in,
                              void* d_out, int out_size) {
    const float* x   = (const float*)d_in[0];
    const int*   src = (const int*)d_in[1];
    const int*   dst = (const int*)d_in[2];
    const float* Ws1 = (const float*)d_in[3];
    const float* Wn1 = (const float*)d_in[4];
    const float* b1  = (const float*)d_in[5];
    const float* Ws2 = (const float*)d_in[6];
    const float* Wn2 = (const float*)d_in[7];
    const float* b2  = (const float*)d_in[8];
    float* out = (float*)d_out;

    const int VB = 256;
    dim3 vgrid((NN + VB - 1) / VB);
    const int EB = 256;
    dim3 egrid((NE / 4 + EB - 1) / EB);
    dim3 vb(VB), eb(EB);

    const int4* src4 = (const int4*)src;
    const int4* dst4 = (const int4*)dst;
    uint4* acc1 = nullptr; cudaGetSymbolAddress((void**)&acc1, g_acc1);
    uint4* acc2 = nullptr; cudaGetSymbolAddress((void**)&acc2, g_acc2);

    {   // prep (no PDL attr; it is the chain head)
        void* args[] = { (void*)&x };
        launch_pdl((void*)k_prep, vgrid, vb, args, false);
    }
    {   // edge1
        void* args[] = { (void*)&src4, (void*)&dst4, (void*)&acc1 };
        launch_pdl((void*)k_edge<1>, egrid, eb, args, true);
    }
    {   // node1
        void* args[] = { (void*)&x, (void*)&Ws1, (void*)&Wn1, (void*)&b1 };
        launch_pdl((void*)k_node1, vgrid, vb, args, true);
    }
    {   // edge2
        void* args[] = { (void*)&src4, (void*)&dst4, (void*)&acc2 };
        launch_pdl((void*)k_edge<0>, egrid, eb, args, true);
    }
    {   // node2
        void* args[] = { (void*)&out, (void*)&Ws2, (void*)&Wn2, (void*)&b2 };
        launch_pdl((void*)k_node2, vgrid, vb, args, true);
    }
}

// round 10
// speedup vs baseline: 1.0518x; 1.0518x over previous
#include <cuda_runtime.h>
#include <cuda_fp16.h>
#include <math.h>

#define NN 100000
#define NE 6400000
#define F1 5     // F_IN
#define F2 5     // F_HID
#define F3 10    // F_OUT

// Scratch (no allocations allowed)
// Packed fp16 gather table: 8 halfs/node = 16B: [f0 f1 f2 f3 f4 degslot pad pad]
__device__ uint4 g_gath16[NN];
// Separate accumulators per layer; deg accumulates in acc1's lane 5 and is
// read again by node2 (acc1 is never re-zeroed between passes).
__device__ uint4 g_acc1[NN];
__device__ uint4 g_acc2[NN];
// Full-precision h for the layer-2 self term
__device__ float g_h32[NN * F2];

__device__ __forceinline__ float sigmoidf_(float z) {
    return 1.0f / (1.0f + __expf(-z));
}

__device__ __forceinline__ unsigned packh2(float a, float b) {
    unsigned lo = __half_as_ushort(__float2half_rn(a));
    unsigned hi = __half_as_ushort(__float2half_rn(b));
    return lo | (hi << 16);
}
__device__ __forceinline__ float loh(unsigned w) {
    return __half2float(__ushort_as_half((unsigned short)(w & 0xFFFF)));
}
__device__ __forceinline__ float hih(unsigned w) {
    return __half2float(__ushort_as_half((unsigned short)(w >> 16)));
}

// Single 16B half-precision vector reduction: 8 half lanes in one LTS op.
__device__ __forceinline__ void red_v4h2(uint4* p, unsigned a, unsigned b,
                                         unsigned c, unsigned d) {
    asm volatile("red.global.add.noftz.v4.f16x2 [%0], {%1, %2, %3, %4};"
                 :: "l"(p), "r"(a), "r"(b), "r"(c), "r"(d) : "memory");
}

// Prep: zero both accumulators, quantize x into packed gather table
__global__ void k_prep(const float* __restrict__ x) {
    cudaTriggerProgrammaticLaunchCompletion();
    int v = blockIdx.x * blockDim.x + threadIdx.x;
    if (v >= NN) return;
    const float* xs = x + v * F1;
    unsigned w0 = packh2(xs[0], xs[1]);
    unsigned w1 = packh2(xs[2], xs[3]);
    unsigned w2 = packh2(xs[4], 0.0f);   // deg slot starts at 0
    g_gath16[v] = make_uint4(w0, w1, w2, 0u);
    g_acc1[v]   = make_uint4(0u, 0u, 0u, 0u);
    g_acc2[v]   = make_uint4(0u, 0u, 0u, 0u);
}

// Edge pass (R4 shape, untouched inner loop): acc[dst] += gath16[src].
// One LDG.128 + one red.v4.f16x2 per edge; 4 edges per thread via int4 loads.
// NE/4 = 1.6M is an exact multiple of 256, so the grid covers exactly: no guard.
// DEG=1: also add 1.0h into the deg lane (high half of word 2).
template <int DEG>
__global__ void __launch_bounds__(256) k_edge(const int4* __restrict__ src4,
                                              const int4* __restrict__ dst4,
                                              uint4* __restrict__ acc) {
    cudaTriggerProgrammaticLaunchCompletion();
    int t = blockIdx.x * blockDim.x + threadIdx.x;
    int4 s4 = __ldg(src4 + t);
    int4 d4 = __ldg(dst4 + t);
    int ss[4] = {s4.x, s4.y, s4.z, s4.w};
    int dd[4] = {d4.x, d4.y, d4.z, d4.w};
    const unsigned degbit = DEG ? 0x3C000000u : 0u;   // +1.0h in deg lane
    uint4 g[4];
#pragma unroll
    for (int k = 0; k < 4; k++) g[k] = __ldg(&g_gath16[ss[k]]);
#pragma unroll
    for (int k = 0; k < 4; k++) {
        red_v4h2(&acc[dd[k]], g[k].x, g[k].y, g[k].z | degbit, g[k].w);
    }
}

// Node pass 1: h = sigmoid(x @ Ws1 + (acc1/deg) @ Wn1 + b1)
// Under PDL: uniform weight/bias loads happen before the grid-dep sync.
__global__ void k_node1(const float* __restrict__ x,
                        const float* __restrict__ Ws,
                        const float* __restrict__ Wn,
                        const float* __restrict__ b) {
    cudaTriggerProgrammaticLaunchCompletion();
    float wS[F1 * F2], wN[F1 * F2], bb[F2];
#pragma unroll
    for (int i = 0; i < F1 * F2; i++) { wS[i] = __ldg(Ws + i); wN[i] = __ldg(Wn + i); }
#pragma unroll
    for (int j = 0; j < F2; j++) bb[j] = __ldg(b + j);
    cudaGridDependencySynchronize();   // wait for edge1's reds
    int v = blockIdx.x * blockDim.x + threadIdx.x;
    if (v >= NN) return;
    float xs[F1];
#pragma unroll
    for (int i = 0; i < F1; i++) xs[i] = x[v * F1 + i];
    uint4 a = g_acc1[v];
    float deg = hih(a.z);
    float inv = 1.0f / fmaxf(deg, 1.0f);
    float xn[F1] = { loh(a.x) * inv, hih(a.x) * inv,
                     loh(a.y) * inv, hih(a.y) * inv,
                     loh(a.z) * inv };
    float h[F2];
#pragma unroll
    for (int j = 0; j < F2; j++) {
        float z = bb[j];
#pragma unroll
        for (int i = 0; i < F1; i++) {
            z = fmaf(xs[i], wS[i * F2 + j], z);
            z = fmaf(xn[i], wN[i * F2 + j], z);
        }
        h[j] = sigmoidf_(z);
    }
#pragma unroll
    for (int j = 0; j < F2; j++) g_h32[v * F2 + j] = h[j];
    // Centered h-0.5 keeps fp16 sums small (|sum| ~ sqrt(deg)/4, not deg/2)
    unsigned w0 = packh2(h[0] - 0.5f, h[1] - 0.5f);
    unsigned w1 = packh2(h[2] - 0.5f, h[3] - 0.5f);
    unsigned w2 = packh2(h[4] - 0.5f, 0.0f);
    g_gath16[v] = make_uint4(w0, w1, w2, 0u);
}

// Node pass 2: out = sigmoid(h @ Ws2 + (acc2_c/deg + 0.5) @ Wn2 + b2)
// deg comes from acc1 (untouched since pass 1).
__global__ void k_node2(float* __restrict__ out,
                        const float* __restrict__ Ws,
                        const float* __restrict__ Wn,
                        const float* __restrict__ b) {
    float wS[F2 * F3], wN[F2 * F3], bb[F3];
#pragma unroll
    for (int i = 0; i < F2 * F3; i++) { wS[i] = __ldg(Ws + i); wN[i] = __ldg(Wn + i); }
#pragma unroll
    for (int j = 0; j < F3; j++) bb[j] = __ldg(b + j);
    cudaGridDependencySynchronize();   // wait for edge2's reds
    int v = blockIdx.x * blockDim.x + threadIdx.x;
    if (v >= NN) return;
    uint4 a = g_acc2[v];
    float deg = hih(g_acc1[v].z);
    float inv = 1.0f / fmaxf(deg, 1.0f);
    // De-center: mean(h) = mean(h-0.5) + 0.5  (only where deg>0; deg==0 gives 0)
    float half_off = (deg > 0.0f) ? 0.5f : 0.0f;
    float hn[F2] = { loh(a.x) * inv + half_off, hih(a.x) * inv + half_off,
                     loh(a.y) * inv + half_off, hih(a.y) * inv + half_off,
                     loh(a.z) * inv + half_off };
    float hs[F2];
#pragma unroll
    for (int i = 0; i < F2; i++) hs[i] = g_h32[v * F2 + i];
#pragma unroll
    for (int j = 0; j < F3; j++) {
        float z = bb[j];
#pragma unroll
        for (int i = 0; i < F2; i++) {
            z = fmaf(hs[i], wS[i * F3 + j], z);
            z = fmaf(hn[i], wN[i * F3 + j], z);
        }
        out[v * F3 + j] = sigmoidf_(z);
    }
}

static inline void launch_pdl(void* fn, dim3 grid, dim3 block,
                              void** args, bool pdl) {
    cudaLaunchConfig_t cfg = {};
    cfg.gridDim = grid;
    cfg.blockDim = block;
    cfg.dynamicSmemBytes = 0;
    cfg.stream = 0;
    cudaLaunchAttribute attr[1];
    if (pdl) {
        attr[0].id = cudaLaunchAttributeProgrammaticStreamSerialization;
        attr[0].val.programmaticStreamSerializationAllowed = 1;
        cfg.attrs = attr;
        cfg.numAttrs = 1;
    }
    cudaLaunchKernelExC(&cfg, fn, args);
}

extern "C" void kernel_launch(void* const* d_in, const int* in_sizes, int n_in,
                              void* d_out, int out_size) {
    const float* x   = (const float*)d_in[0];
    const int*   src = (const int*)d_in[1];
    const int*   dst = (const int*)d_in[2];
    const float* Ws1 = (const float*)d_in[3];
    const float* Wn1 = (const float*)d_in[4];
    const float* b1  = (const float*)d_in[5];
    const float* Ws2 = (const float*)d_in[6];
    const float* Wn2 = (const float*)d_in[7];
    const float* b2  = (const float*)d_in[8];
    float* out = (float*)d_out;

    const int VB = 256;
    dim3 vgrid((NN + VB - 1) / VB);
    const int EB = 256;
    dim3 egrid(NE / 4 / EB);   // exact: 6250 blocks
    dim3 vb(VB), eb(EB);

    const int4* src4 = (const int4*)src;
    const int4* dst4 = (const int4*)dst;
    uint4* acc1 = nullptr; cudaGetSymbolAddress((void**)&acc1, g_acc1);
    uint4* acc2 = nullptr; cudaGetSymbolAddress((void**)&acc2, g_acc2);

    {   // prep (chain head, plain launch)
        void* args[] = { (void*)&x };
        launch_pdl((void*)k_prep, vgrid, vb, args, false);
    }
    {   // edge1 — plain serialization (its consumer releases it; no early work)
        void* args[] = { (void*)&src4, (void*)&dst4, (void*)&acc1 };
        launch_pdl((void*)k_edge<1>, egrid, eb, args, false);
    }
    {   // node1 — PDL: prologue (weights) overlaps edge1 tail
        void* args[] = { (void*)&x, (void*)&Ws1, (void*)&Wn1, (void*)&b1 };
        launch_pdl((void*)k_node1, vgrid, vb, args, true);
    }
    {   // edge2 — plain
        void* args[] = { (void*)&src4, (void*)&dst4, (void*)&acc2 };
        launch_pdl((void*)k_edge<0>, egrid, eb, args, false);
    }
    {   // node2 — PDL
        void* args[] = { (void*)&out, (void*)&Ws2, (void*)&Wn2, (void*)&b2 };
        launch_pdl((void*)k_node2, vgrid, vb, args, true);
    }
}

// round 11
// speedup vs baseline: 1.0714x; 1.0187x over previous
#include <cuda_runtime.h>
#include <cuda_fp16.h>
#include <math.h>

#define NN 100000
#define NE 6400000
#define F1 5     // F_IN
#define F2 5     // F_HID
#define F3 10    // F_OUT

// Scratch (no allocations allowed)
// Packed fp16 gather table: 8 halfs/node = 16B: [f0 f1 f2 f3 f4 degslot pad pad]
__device__ uint4 g_gath16[NN];
// Separate accumulators per layer; deg accumulates in acc1's lane 5 and is
// read again by node2 (acc1 is never re-zeroed between passes).
__device__ uint4 g_acc1[NN];
__device__ uint4 g_acc2[NN];
// Full-precision h for the layer-2 self term
__device__ float g_h32[NN * F2];

__device__ __forceinline__ float sigmoidf_(float z) {
    return 1.0f / (1.0f + __expf(-z));
}

__device__ __forceinline__ unsigned packh2(float a, float b) {
    unsigned lo = __half_as_ushort(__float2half_rn(a));
    unsigned hi = __half_as_ushort(__float2half_rn(b));
    return lo | (hi << 16);
}
__device__ __forceinline__ float loh(unsigned w) {
    return __half2float(__ushort_as_half((unsigned short)(w & 0xFFFF)));
}
__device__ __forceinline__ float hih(unsigned w) {
    return __half2float(__ushort_as_half((unsigned short)(w >> 16)));
}

// Single 16B half-precision vector reduction: 8 half lanes in one LTS op.
__device__ __forceinline__ void red_v4h2(uint4* p, unsigned a, unsigned b,
                                         unsigned c, unsigned d) {
    asm volatile("red.global.add.noftz.v4.f16x2 [%0], {%1, %2, %3, %4};"
                 :: "l"(p), "r"(a), "r"(b), "r"(c), "r"(d) : "memory");
}

// Prep: zero both accumulators, quantize x into packed gather table
__global__ void k_prep(const float* __restrict__ x) {
    cudaTriggerProgrammaticLaunchCompletion();
    int v = blockIdx.x * blockDim.x + threadIdx.x;
    if (v >= NN) return;
    const float* xs = x + v * F1;
    unsigned w0 = packh2(xs[0], xs[1]);
    unsigned w1 = packh2(xs[2], xs[3]);
    unsigned w2 = packh2(xs[4], 0.0f);   // deg slot starts at 0
    g_gath16[v] = make_uint4(w0, w1, w2, 0u);
    g_acc1[v]   = make_uint4(0u, 0u, 0u, 0u);
    g_acc2[v]   = make_uint4(0u, 0u, 0u, 0u);
}

// Edge pass (floor shape, untouched inner loop): acc[dst] += gath16[src].
// One LDG.128 + one red.v4.f16x2 per edge; 4 edges per thread via int4 loads.
// NE/4 = 1.6M is an exact multiple of 256, so the grid covers exactly: no guard.
// PDL: trigger lets the successor launch early; sync (before ANY loads, no
// restructure) waits for the predecessor's data.
// DEG=1: also add 1.0h into the deg lane (high half of word 2).
template <int DEG>
__global__ void __launch_bounds__(256) k_edge(const int4* __restrict__ src4,
                                              const int4* __restrict__ dst4,
                                              uint4* __restrict__ acc) {
    cudaTriggerProgrammaticLaunchCompletion();
    cudaGridDependencySynchronize();
    int t = blockIdx.x * blockDim.x + threadIdx.x;
    int4 s4 = __ldg(src4 + t);
    int4 d4 = __ldg(dst4 + t);
    int ss[4] = {s4.x, s4.y, s4.z, s4.w};
    int dd[4] = {d4.x, d4.y, d4.z, d4.w};
    const unsigned degbit = DEG ? 0x3C000000u : 0u;   // +1.0h in deg lane
    uint4 g[4];
#pragma unroll
    for (int k = 0; k < 4; k++) g[k] = __ldg(&g_gath16[ss[k]]);
#pragma unroll
    for (int k = 0; k < 4; k++) {
        red_v4h2(&acc[dd[k]], g[k].x, g[k].y, g[k].z | degbit, g[k].w);
    }
}

// Node pass 1: h = sigmoid(x @ Ws1 + (acc1/deg) @ Wn1 + b1)
// Under PDL: uniform weight/bias loads happen before the grid-dep sync.
__global__ void k_node1(const float* __restrict__ x,
                        const float* __restrict__ Ws,
                        const float* __restrict__ Wn,
                        const float* __restrict__ b) {
    cudaTriggerProgrammaticLaunchCompletion();
    float wS[F1 * F2], wN[F1 * F2], bb[F2];
#pragma unroll
    for (int i = 0; i < F1 * F2; i++) { wS[i] = __ldg(Ws + i); wN[i] = __ldg(Wn + i); }
#pragma unroll
    for (int j = 0; j < F2; j++) bb[j] = __ldg(b + j);
    cudaGridDependencySynchronize();   // wait for edge1's reds
    int v = blockIdx.x * blockDim.x + threadIdx.x;
    if (v >= NN) return;
    float xs[F1];
#pragma unroll
    for (int i = 0; i < F1; i++) xs[i] = x[v * F1 + i];
    uint4 a = g_acc1[v];
    float deg = hih(a.z);
    float inv = 1.0f / fmaxf(deg, 1.0f);
    float xn[F1] = { loh(a.x) * inv, hih(a.x) * inv,
                     loh(a.y) * inv, hih(a.y) * inv,
                     loh(a.z) * inv };
    float h[F2];
#pragma unroll
    for (int j = 0; j < F2; j++) {
        float z = bb[j];
#pragma unroll
        for (int i = 0; i < F1; i++) {
            z = fmaf(xs[i], wS[i * F2 + j], z);
            z = fmaf(xn[i], wN[i * F2 + j], z);
        }
        h[j] = sigmoidf_(z);
    }
#pragma unroll
    for (int j = 0; j < F2; j++) g_h32[v * F2 + j] = h[j];
    // Centered h-0.5 keeps fp16 sums small (|sum| ~ sqrt(deg)/4, not deg/2)
    unsigned w0 = packh2(h[0] - 0.5f, h[1] - 0.5f);
    unsigned w1 = packh2(h[2] - 0.5f, h[3] - 0.5f);
    unsigned w2 = packh2(h[4] - 0.5f, 0.0f);
    g_gath16[v] = make_uint4(w0, w1, w2, 0u);
}

// Node pass 2: out = sigmoid(h @ Ws2 + (acc2_c/deg + 0.5) @ Wn2 + b2)
// deg comes from acc1 (untouched since pass 1).
__global__ void k_node2(float* __restrict__ out,
                        const float* __restrict__ Ws,
                        const float* __restrict__ Wn,
                        const float* __restrict__ b) {
    float wS[F2 * F3], wN[F2 * F3], bb[F3];
#pragma unroll
    for (int i = 0; i < F2 * F3; i++) { wS[i] = __ldg(Ws + i); wN[i] = __ldg(Wn + i); }
#pragma unroll
    for (int j = 0; j < F3; j++) bb[j] = __ldg(b + j);
    cudaGridDependencySynchronize();   // wait for edge2's reds
    int v = blockIdx.x * blockDim.x + threadIdx.x;
    if (v >= NN) return;
    uint4 a = g_acc2[v];
    float deg = hih(g_acc1[v].z);
    float inv = 1.0f / fmaxf(deg, 1.0f);
    // De-center: mean(h) = mean(h-0.5) + 0.5  (only where deg>0; deg==0 gives 0)
    float half_off = (deg > 0.0f) ? 0.5f : 0.0f;
    float hn[F2] = { loh(a.x) * inv + half_off, hih(a.x) * inv + half_off,
                     loh(a.y) * inv + half_off, hih(a.y) * inv + half_off,
                     loh(a.z) * inv + half_off };
    float hs[F2];
#pragma unroll
    for (int i = 0; i < F2; i++) hs[i] = g_h32[v * F2 + i];
#pragma unroll
    for (int j = 0; j < F3; j++) {
        float z = bb[j];
#pragma unroll
        for (int i = 0; i < F2; i++) {
            z = fmaf(hs[i], wS[i * F3 + j], z);
            z = fmaf(hn[i], wN[i * F3 + j], z);
        }
        out[v * F3 + j] = sigmoidf_(z);
    }
}

static inline void launch_pdl(void* fn, dim3 grid, dim3 block,
                              void** args, bool pdl) {
    cudaLaunchConfig_t cfg = {};
    cfg.gridDim = grid;
    cfg.blockDim = block;
    cfg.dynamicSmemBytes = 0;
    cfg.stream = 0;
    cudaLaunchAttribute attr[1];
    if (pdl) {
        attr[0].id = cudaLaunchAttributeProgrammaticStreamSerialization;
        attr[0].val.programmaticStreamSerializationAllowed = 1;
        cfg.attrs = attr;
        cfg.numAttrs = 1;
    }
    cudaLaunchKernelExC(&cfg, fn, args);
}

extern "C" void kernel_launch(void* const* d_in, const int* in_sizes, int n_in,
                              void* d_out, int out_size) {
    const float* x   = (const float*)d_in[0];
    const int*   src = (const int*)d_in[1];
    const int*   dst = (const int*)d_in[2];
    const float* Ws1 = (const float*)d_in[3];
    const float* Wn1 = (const float*)d_in[4];
    const float* b1  = (const float*)d_in[5];
    const float* Ws2 = (const float*)d_in[6];
    const float* Wn2 = (const float*)d_in[7];
    const float* b2  = (const float*)d_in[8];
    float* out = (float*)d_out;

    const int VB = 256;
    dim3 vgrid((NN + VB - 1) / VB);
    const int EB = 256;
    dim3 egrid(NE / 4 / EB);   // exact: 6250 blocks
    dim3 vb(VB), eb(EB);

    const int4* src4 = (const int4*)src;
    const int4* dst4 = (const int4*)dst;
    uint4* acc1 = nullptr; cudaGetSymbolAddress((void**)&acc1, g_acc1);
    uint4* acc2 = nullptr; cudaGetSymbolAddress((void**)&acc2, g_acc2);

    {   // prep (chain head, plain launch)
        void* args[] = { (void*)&x };
        launch_pdl((void*)k_prep, vgrid, vb, args, false);
    }
    {   // edge1 — PDL: blocks resident early, sync at top, body untouched
        void* args[] = { (void*)&src4, (void*)&dst4, (void*)&acc1 };
        launch_pdl((void*)k_edge<1>, egrid, eb, args, true);
    }
    {   // node1 — PDL: prologue (weights) overlaps edge1 tail
        void* args[] = { (void*)&x, (void*)&Ws1, (void*)&Wn1, (void*)&b1 };
        launch_pdl((void*)k_node1, vgrid, vb, args, true);
    }
    {   // edge2 — PDL
        void* args[] = { (void*)&src4, (void*)&dst4, (void*)&acc2 };
        launch_pdl((void*)k_edge<0>, egrid, eb, args, true);
    }
    {   // node2 — PDL
        void* args[] = { (void*)&out, (void*)&Ws2, (void*)&Wn2, (void*)&b2 };
        launch_pdl((void*)k_node2, vgrid, vb, args, true);
    }
}